// round 16
// baseline (speedup 1.0000x reference)
#include <cuda_runtime.h>
#include <cuda_fp16.h>
#include <cstdint>

#define D_DIM 64
#define K_DIM 512
#define TILE_ROWS 32
#define THREADS 256
#define MARGIN 1.0f
#define DPITCH_H 520     // dist pitch in halves

// ---------------- device scratch (no cudaMalloc allowed) ----------------
__device__ float g_Et[K_DIM * D_DIM];    // exact fp32 E, code-major [k][d]

// ---------------- smem layout (bytes), total 109.5 KB -> 2 CTAs/SM ----------------
#define SM_EH    0                                    // [64][512] half  = 65536
#define SM_XH    (SM_EH + D_DIM * K_DIM * 2)          // [32][64] half2  = 8192 (dup -2x)
#define SM_SE2   (SM_XH + TILE_ROWS * D_DIM * 4)      // [512] f32       = 2048
#define SM_PVAL  (SM_SE2 + K_DIM * 4)                 // [2][32] f32     = 256
#define SM_RTHR  (SM_PVAL + 256)                      // [32] f32        = 128
#define SM_KFIN  (SM_RTHR + 128)                      // [32] i32        = 128
#define SM_DIST  (SM_KFIN + 128)                      // [32][520] half  = 33280
#define SM_TOTAL (SM_DIST + TILE_ROWS * DPITCH_H * 2) // 109568

// ---------------- prep: transpose E to code-major ----------------
__global__ void vq_prep(const float* __restrict__ emb) {
    int i = blockIdx.x * blockDim.x + threadIdx.x;
    if (i < K_DIM * D_DIM) {
        int k = i / D_DIM, d = i % D_DIM;
        g_Et[i] = emb[d * K_DIM + k];
    }
}

// exact fp32 distance: x row and E row from gmem (both L2-hot). Fully
// unrolled -> ~16 independent LDG.128 pairs in flight (high MLP).
__device__ __forceinline__ float exact_dist(const float4* __restrict__ x4,
                                            int k, float se2k) {
    const float4* er = (const float4*)(g_Et + k * D_DIM);
    float d0 = 0.f, d1 = 0.f;
    #pragma unroll
    for (int q = 0; q < 16; q += 2) {
        float4 ea = er[q],     xa = __ldg(x4 + q);
        float4 eb = er[q + 1], xb = __ldg(x4 + q + 1);
        d0 = fmaf(xa.x, ea.x, d0); d0 = fmaf(xa.y, ea.y, d0);
        d0 = fmaf(xa.z, ea.z, d0); d0 = fmaf(xa.w, ea.w, d0);
        d1 = fmaf(xb.x, eb.x, d1); d1 = fmaf(xb.y, eb.y, d1);
        d1 = fmaf(xb.z, eb.z, d1); d1 = fmaf(xb.w, eb.w, d1);
    }
    return fmaf(-2.f, d0 + d1, se2k);
}

// ---------------- main ----------------
__global__ void __launch_bounds__(THREADS, 2)
vq_main(const float* __restrict__ x, const float* __restrict__ emb,
        float* __restrict__ out, int nrows, int ntiles)
{
    extern __shared__ char smem[];
    __half*  sEh  = (__half*) (smem + SM_EH);    // [d][k] fp16 codebook
    __half2* sxh  = (__half2*)(smem + SM_XH);    // [row][d] dup {-2x,-2x}
    float*   se2s = (float*)  (smem + SM_SE2);
    float*   pval = (float*)  (smem + SM_PVAL);  // [2][32]
    float*   rthr = (float*)  (smem + SM_RTHR);
    int*     kfin = (int*)    (smem + SM_KFIN);
    __half*  dist = (__half*) (smem + SM_DIST);  // raw -2x.e accumulators

    const int tid  = threadIdx.x;
    const int warp = tid >> 5;
    const int lane = tid & 31;
    const int g    = warp & 3;            // row group: rows g*8..+7
    const int h    = warp >> 2;           // K half: codes h*256..+255
    const int r0   = g * 8;
    const int kbase = h * 256 + lane * 8; // lane owns 8 consecutive codes

    // ---- one-time: fp16 codebook (emb is already [d][k]) + exact ||e||^2 ----
    for (int i = tid; i < D_DIM * K_DIM / 4; i += THREADS) {
        float4 v = *(const float4*)(emb + i * 4);
        __half2 h0 = __floats2half2_rn(v.x, v.y);
        __half2 h1 = __floats2half2_rn(v.z, v.w);
        uint2 pk;
        pk.x = *(uint32_t*)&h0; pk.y = *(uint32_t*)&h1;
        *(uint2*)(sEh + i * 4) = pk;
    }
    for (int k = tid; k < K_DIM; k += THREADS) {
        const float* er = g_Et + k * D_DIM;
        float s = 0.f;
        #pragma unroll 8
        for (int d = 0; d < D_DIM; d++) s = fmaf(er[d], er[d], s);
        se2s[k] = s;
    }
    __syncthreads();

    for (int tile = blockIdx.x; tile < ntiles; tile += gridDim.x) {
        const int rowbase = tile * TILE_ROWS;

        // ---- load x tile as dup'd fp16 (-2x): 2 float4 per thread ----
        for (int i = tid; i < TILE_ROWS * D_DIM / 4; i += THREADS) {
            int row = i >> 4, d4 = (i & 15) * 4;
            int grow = rowbase + row;
            float4 v = (grow < nrows) ? __ldg((const float4*)(x + (size_t)grow * D_DIM + d4))
                                      : make_float4(0.f, 0.f, 0.f, 0.f);
            __half2 a = __floats2half2_rn(-2.f * v.x, -2.f * v.x);
            __half2 b = __floats2half2_rn(-2.f * v.y, -2.f * v.y);
            __half2 c = __floats2half2_rn(-2.f * v.z, -2.f * v.z);
            __half2 e = __floats2half2_rn(-2.f * v.w, -2.f * v.w);
            uint4 pk;
            pk.x = *(uint32_t*)&a; pk.y = *(uint32_t*)&b;
            pk.z = *(uint32_t*)&c; pk.w = *(uint32_t*)&e;
            *(uint4*)(sxh + row * D_DIM + d4) = pk;
        }
        __syncthreads();

        // ---- HFMA2 mainloop: warp = 8 rows x 256 codes, lane = 8 codes ----
        __half2 acc[8][4];
        const __half2 z = __floats2half2_rn(0.f, 0.f);
        #pragma unroll
        for (int r = 0; r < 8; r++) {
            acc[r][0] = z; acc[r][1] = z; acc[r][2] = z; acc[r][3] = z;
        }

        const __half* ebase = sEh + kbase;
        #pragma unroll 2
        for (int d0 = 0; d0 < D_DIM; d0 += 2) {
            uint2 xw[8];
            #pragma unroll
            for (int r = 0; r < 8; r++)
                xw[r] = *(const uint2*)(sxh + (r0 + r) * D_DIM + d0);   // broadcast LDS.64

            uint4 ew0 = *(const uint4*)(ebase + d0 * K_DIM);            // 8 codes @ d0
            uint4 ew1 = *(const uint4*)(ebase + (d0 + 1) * K_DIM);      // 8 codes @ d0+1

            __half2 e00 = *(__half2*)&ew0.x, e01 = *(__half2*)&ew0.y;
            __half2 e02 = *(__half2*)&ew0.z, e03 = *(__half2*)&ew0.w;
            __half2 e10 = *(__half2*)&ew1.x, e11 = *(__half2*)&ew1.y;
            __half2 e12 = *(__half2*)&ew1.z, e13 = *(__half2*)&ew1.w;

            #pragma unroll
            for (int r = 0; r < 8; r++) {
                __half2 x0 = *(__half2*)&xw[r].x;   // dup(-2x[d0])
                __half2 x1 = *(__half2*)&xw[r].y;   // dup(-2x[d0+1])
                acc[r][0] = __hfma2(e00, x0, acc[r][0]);
                acc[r][1] = __hfma2(e01, x0, acc[r][1]);
                acc[r][2] = __hfma2(e02, x0, acc[r][2]);
                acc[r][3] = __hfma2(e03, x0, acc[r][3]);
                acc[r][0] = __hfma2(e10, x1, acc[r][0]);
                acc[r][1] = __hfma2(e11, x1, acc[r][1]);
                acc[r][2] = __hfma2(e12, x1, acc[r][2]);
                acc[r][3] = __hfma2(e13, x1, acc[r][3]);
            }
        }

        // ---- store raw accumulators to dist + per-lane best value per row ----
        float bestv[8];
        {
            float4 s2a = *(const float4*)(se2s + kbase);
            float4 s2b = *(const float4*)(se2s + kbase + 4);
            #pragma unroll
            for (int r = 0; r < 8; r++) {
                uint4 pk;
                pk.x = *(uint32_t*)&acc[r][0]; pk.y = *(uint32_t*)&acc[r][1];
                pk.z = *(uint32_t*)&acc[r][2]; pk.w = *(uint32_t*)&acc[r][3];
                *(uint4*)(dist + (r0 + r) * DPITCH_H + kbase) = pk;

                float2 f0 = __half22float2(acc[r][0]);
                float2 f1 = __half22float2(acc[r][1]);
                float2 f2 = __half22float2(acc[r][2]);
                float2 f3 = __half22float2(acc[r][3]);
                float m = fminf(fminf(f0.x + s2a.x, f0.y + s2a.y),
                                fminf(f1.x + s2a.z, f1.y + s2a.w));
                m = fminf(m, fminf(fminf(f2.x + s2b.x, f2.y + s2b.y),
                                   fminf(f3.x + s2b.z, f3.y + s2b.w)));
                bestv[r] = m;
            }
        }
        #pragma unroll
        for (int r = 0; r < 8; r++) {
            float mv = bestv[r];
            #pragma unroll
            for (int off = 16; off; off >>= 1)
                mv = fminf(mv, __shfl_xor_sync(0xffffffffu, mv, off));
            if (lane == 0) pval[h * 32 + r0 + r] = mv;
        }
        __syncthreads();

        // merge the two K-halves -> per-row threshold
        if (tid < TILE_ROWS)
            rthr[tid] = fminf(pval[tid], pval[32 + tid]) + MARGIN;
        __syncthreads();

        // ---- scan: candidates from stored scores, exact fp32 rescore ----
        // warp -> 4 rows; lane -> 16 codes of that row
        for (int rr = 0; rr < 4; rr++) {
            const int row = warp * 4 + rr;
            const int grow = rowbase + row;
            const float thr = rthr[row];
            const float4* x4 = (const float4*)(x + (size_t)grow * D_DIM);
            const __half* drow = dist + row * DPITCH_H + lane * 16;

            // vectorized se2 for this lane's 16 codes (no 16-way bank conflict)
            float4 sv[4];
            sv[0] = *(const float4*)(se2s + lane * 16);
            sv[1] = *(const float4*)(se2s + lane * 16 + 4);
            sv[2] = *(const float4*)(se2s + lane * 16 + 8);
            sv[3] = *(const float4*)(se2s + lane * 16 + 12);
            const float* svp = (const float*)sv;

            uint4 w0 = *(const uint4*)(drow);
            uint4 w1 = *(const uint4*)(drow + 8);
            const uint32_t ws[8] = { w0.x, w0.y, w0.z, w0.w, w1.x, w1.y, w1.z, w1.w };

            float ev = 3.4e38f; int ek = 0x7fffffff;
            #pragma unroll
            for (int q = 0; q < 8; q++) {
                float2 f = __half22float2(*(const __half2*)&ws[q]);
                int k0 = lane * 16 + q * 2;
                float sa = f.x + svp[q * 2];
                float sb = f.y + svp[q * 2 + 1];
                if (sa <= thr) {
                    float s = exact_dist(x4, k0, svp[q * 2]);
                    if (s < ev || (s == ev && k0 < ek)) { ev = s; ek = k0; }
                }
                if (sb <= thr) {
                    float s = exact_dist(x4, k0 + 1, svp[q * 2 + 1]);
                    if (s < ev || (s == ev && k0 + 1 < ek)) { ev = s; ek = k0 + 1; }
                }
            }
            #pragma unroll
            for (int off = 16; off; off >>= 1) {
                float ov = __shfl_xor_sync(0xffffffffu, ev, off);
                int   ok = __shfl_xor_sync(0xffffffffu, ek, off);
                if (ov < ev || (ov == ev && ok < ek)) { ev = ov; ek = ok; }
            }
            if (lane == 0) kfin[row] = ek;
        }
        __syncthreads();

        // ---- gather exact E row + store (4 threads/row x 16 floats) ----
        if (tid < TILE_ROWS * 4) {
            int row = tid >> 2, part = tid & 3;
            int grow = rowbase + row;
            if (grow < nrows) {
                const float4* src = (const float4*)(g_Et + kfin[row] * D_DIM + part * 16);
                float4* dst = (float4*)(out + (size_t)grow * D_DIM + part * 16);
                dst[0] = src[0]; dst[1] = src[1]; dst[2] = src[2]; dst[3] = src[3];
            }
        }
        __syncthreads();   // smem reuse guard for next tile
    }
}

extern "C" void kernel_launch(void* const* d_in, const int* in_sizes, int n_in,
                              void* d_out, int out_size)
{
    const float* x   = (const float*)d_in[0];   // inputs [B,H,W,D] fp32
    const float* emb = (const float*)d_in[1];   // embeddings [D,K] fp32
    float* out = (float*)d_out;

    int nrows  = in_sizes[0] / D_DIM;
    int ntiles = (nrows + TILE_ROWS - 1) / TILE_ROWS;

    vq_prep<<<(K_DIM * D_DIM + 511) / 512, 512>>>(emb);

    cudaFuncSetAttribute(vq_main, cudaFuncAttributeMaxDynamicSharedMemorySize, SM_TOTAL);
    int grid = 296;                      // 2 CTAs x 148 SMs
    if (grid > ntiles) grid = ntiles;
    vq_main<<<grid, THREADS, SM_TOTAL>>>(x, emb, out, nrows, ntiles);
}

// round 17
// speedup vs baseline: 2.4106x; 2.4106x over previous
#include <cuda_runtime.h>

#define D_DIM 64
#define K_DIM 512
#define K_PAD 516          // pad: keeps 16B alignment, breaks gather conflicts
#define TILE_ROWS 64
#define THREADS 512
#define NBLOCKS 148

typedef unsigned long long ull;

__device__ __forceinline__ ull pack_dup(float x) {
    ull r;
    asm("mov.b64 %0, {%1, %1};" : "=l"(r) : "f"(x));
    return r;
}

__device__ __forceinline__ void fma2(ull& d, ull a, ull b) {
    asm("fma.rn.f32x2 %0, %1, %2, %0;" : "+l"(d) : "l"(a), "l"(b));
}

__device__ __forceinline__ float2 unpack2(ull v) {
    float2 f;
    asm("mov.b64 {%0, %1}, %2;" : "=f"(f.x), "=f"(f.y) : "l"(v));
    return f;
}

// smem layout: sE[64][516] | se2[512] | sx[64][64]
#define SMEM_FLOATS (D_DIM * K_PAD + K_DIM + TILE_ROWS * D_DIM)

__global__ void __launch_bounds__(THREADS, 1)
vq_kernel(const float* __restrict__ x, const float* __restrict__ emb,
          float* __restrict__ out, int nrows, int ntiles)
{
    extern __shared__ float smem[];
    float* sE  = smem;                  // [64][516]
    float* se2 = sE + D_DIM * K_PAD;    // [512]
    float* sx  = se2 + K_DIM;           // [64][64]

    const int tid = threadIdx.x;

    // ---- Load codebook E[d][k] into padded smem (coalesced gmem float4 reads) ----
    for (int i = tid; i < D_DIM * K_DIM / 4; i += THREADS) {
        int d = (i * 4) / K_DIM;
        int k = (i * 4) % K_DIM;
        float4 v = *(const float4*)(emb + d * K_DIM + k);
        *(float4*)(sE + d * K_PAD + k) = v;
    }
    __syncthreads();

    // ---- ||e_k||^2 ----  (512 threads, one k each)
    if (tid < K_DIM) {
        int k = tid;
        float s = 0.f;
        #pragma unroll 8
        for (int d = 0; d < D_DIM; d++) {
            float v = sE[d * K_PAD + k];
            s = fmaf(v, v, s);
        }
        se2[k] = s;
    }

    const int warp = tid >> 5;
    const int lane = tid & 31;
    const int r0 = warp * 4;            // 4 rows per warp, 16 warps -> 64-row tile

    for (int tile = blockIdx.x; tile < ntiles; tile += gridDim.x) {
        const int rowbase = tile * TILE_ROWS;

        __syncthreads();  // protect sx from readers of previous tile (also orders E/e2 on first iter)
        // ---- Load x tile (64 rows x 64 floats), coalesced float4 ----
        {
            const int total4 = TILE_ROWS * D_DIM / 4;
            const float* src = x + (size_t)rowbase * D_DIM;
            const int lim4 = (nrows - rowbase) * D_DIM / 4;  // guard partial last tile
            for (int i = tid; i < total4; i += THREADS) {
                float4 v = (i < lim4) ? *(const float4*)(src + i * 4)
                                      : make_float4(0.f, 0.f, 0.f, 0.f);
                *(float4*)(sx + i * 4) = v;
            }
        }
        __syncthreads();

        float minv[4];
        int   mini[4];
        #pragma unroll
        for (int r = 0; r < 4; r++) { minv[r] = 3.4e38f; mini[r] = 0; }

        // Two K-passes of 256 cols; lane owns cols {4*lane..+3} and {4*lane+128..+3}
        #pragma unroll
        for (int p = 0; p < 2; p++) {
            const int kbase = p * 256 + 4 * lane;

            ull acc[4][4];
            #pragma unroll
            for (int r = 0; r < 4; r++) {
                acc[r][0] = 0ull; acc[r][1] = 0ull; acc[r][2] = 0ull; acc[r][3] = 0ull;
            }

            #pragma unroll 4
            for (int d0 = 0; d0 < D_DIM; d0 += 4) {
                float4 xf[4];
                #pragma unroll
                for (int r = 0; r < 4; r++)
                    xf[r] = *(const float4*)(sx + (r0 + r) * D_DIM + d0);  // broadcast

                #pragma unroll
                for (int dd = 0; dd < 4; dd++) {
                    const float* eptr = sE + (d0 + dd) * K_PAD + kbase;
                    ulonglong2 e0 = *(const ulonglong2*)(eptr);         // cols kbase..+3
                    ulonglong2 e1 = *(const ulonglong2*)(eptr + 128);   // cols kbase+128..+3
                    #pragma unroll
                    for (int r = 0; r < 4; r++) {
                        float xs = (dd == 0) ? xf[r].x : (dd == 1) ? xf[r].y
                                 : (dd == 2) ? xf[r].z : xf[r].w;
                        ull xp = pack_dup(xs);
                        fma2(acc[r][0], xp, e0.x);
                        fma2(acc[r][1], xp, e0.y);
                        fma2(acc[r][2], xp, e1.x);
                        fma2(acc[r][3], xp, e1.y);
                    }
                }
            }

            // se2 for this lane's 8 columns (row-independent -> hoisted out of r loop)
            float4 s2a = *(const float4*)(se2 + kbase);         // cols kbase..+3
            float4 s2b = *(const float4*)(se2 + kbase + 128);   // cols kbase+128..+3

            // Scores + running argmin (k processed in strictly increasing order
            // within a lane -> strict '<' keeps first occurrence, matching jnp.argmin)
            #pragma unroll
            for (int r = 0; r < 4; r++) {
                float2 d0v = unpack2(acc[r][0]);
                float2 d1v = unpack2(acc[r][1]);
                float2 d2v = unpack2(acc[r][2]);
                float2 d3v = unpack2(acc[r][3]);
                float s0 = fmaf(-2.f, d0v.x, s2a.x);
                float s1 = fmaf(-2.f, d0v.y, s2a.y);
                float s2 = fmaf(-2.f, d1v.x, s2a.z);
                float s3 = fmaf(-2.f, d1v.y, s2a.w);
                float s4 = fmaf(-2.f, d2v.x, s2b.x);
                float s5 = fmaf(-2.f, d2v.y, s2b.y);
                float s6 = fmaf(-2.f, d3v.x, s2b.z);
                float s7 = fmaf(-2.f, d3v.y, s2b.w);
                if (s0 < minv[r]) { minv[r] = s0; mini[r] = kbase;     }
                if (s1 < minv[r]) { minv[r] = s1; mini[r] = kbase + 1; }
                if (s2 < minv[r]) { minv[r] = s2; mini[r] = kbase + 2; }
                if (s3 < minv[r]) { minv[r] = s3; mini[r] = kbase + 3; }
                if (s4 < minv[r]) { minv[r] = s4; mini[r] = kbase + 128; }
                if (s5 < minv[r]) { minv[r] = s5; mini[r] = kbase + 129; }
                if (s6 < minv[r]) { minv[r] = s6; mini[r] = kbase + 130; }
                if (s7 < minv[r]) { minv[r] = s7; mini[r] = kbase + 131; }
            }
        }

        // ---- Warp argmin reduction (tie -> smaller k) + gather + write ----
        #pragma unroll
        for (int r = 0; r < 4; r++) {
            float v = minv[r];
            int   ki = mini[r];
            #pragma unroll
            for (int off = 16; off > 0; off >>= 1) {
                float ov = __shfl_down_sync(0xffffffffu, v, off);
                int   oi = __shfl_down_sync(0xffffffffu, ki, off);
                if (ov < v || (ov == v && oi < ki)) { v = ov; ki = oi; }
            }
            ki = __shfl_sync(0xffffffffu, ki, 0);

            int row = rowbase + r0 + r;
            if (row < nrows) {
                float2 o;
                o.x = sE[(2 * lane)     * K_PAD + ki];
                o.y = sE[(2 * lane + 1) * K_PAD + ki];
                *(float2*)(out + (size_t)row * D_DIM + 2 * lane) = o;
            }
        }
    }
}

extern "C" void kernel_launch(void* const* d_in, const int* in_sizes, int n_in,
                              void* d_out, int out_size)
{
    const float* x   = (const float*)d_in[0];   // inputs [B,H,W,D] fp32
    const float* emb = (const float*)d_in[1];   // embeddings [D,K] fp32
    float* out = (float*)d_out;

    int nrows  = in_sizes[0] / D_DIM;
    int ntiles = (nrows + TILE_ROWS - 1) / TILE_ROWS;

    size_t smem_bytes = SMEM_FLOATS * sizeof(float);   // 150528 B
    cudaFuncSetAttribute(vq_kernel, cudaFuncAttributeMaxDynamicSharedMemorySize,
                         (int)smem_bytes);

    int grid = NBLOCKS;
    if (grid > ntiles) grid = ntiles;
    vq_kernel<<<grid, THREADS, smem_bytes>>>(x, emb, out, nrows, ntiles);
}